// round 12
// baseline (speedup 1.0000x reference)
#include <cuda_runtime.h>

// Conv2D 7x7, stride 1, pad 3. X [64,1024,1024] fp32 -> out [64,1024,1024].
// R12: R11 structure (ir-outer single-load-per-row + FFMA2 phase trick +
// cp.async double-buffer, one barrier/chunk, YGROUPS=4) with weights moved
// from __constant__ (LDC floor=8, half-rate const port) to SMEM broadcast
// LDS.128 (floor=2), and acc zero-init replaced by mul.rn.f32x2 first-write.

#define IMG 1024
#define KS 7
#define PAD 3

#define BX 32
#define BY 8
#define TX 4
#define TY 4
#define TILE_W (BX * TX)           // 128
#define CHUNK_H (BY * TY)          // 32 output rows per chunk
#define YGROUPS 4
#define YSPAN (IMG / YGROUPS)      // 256
#define NCHUNK (YSPAN / CHUNK_H)   // 8

#define IN_H (CHUNK_H + KS - 1)    // 38 input rows per chunk
#define PITCH 136                  // floats per smem row (544B, 16B-aligned)

typedef unsigned long long ull;

__device__ __forceinline__ void ffma2(ull& d, ull a, ull b) {
    asm("fma.rn.f32x2 %0, %1, %2, %0;" : "+l"(d) : "l"(a), "l"(b));
}
__device__ __forceinline__ void fmul2(ull& d, ull a, ull b) {
    asm("mul.rn.f32x2 %0, %1, %2;" : "=l"(d) : "l"(a), "l"(b));
}
__device__ __forceinline__ void unpack2(ull v, float& lo, float& hi) {
    asm("mov.b64 {%0, %1}, %2;" : "=f"(lo), "=f"(hi) : "l"(v));
}
__device__ __forceinline__ void cp_wait_all() {
    asm volatile("cp.async.wait_group 0;");
}
__device__ __forceinline__ void cp16(float* dst_smem, const float* src, bool ok) {
    unsigned saddr = (unsigned)__cvta_generic_to_shared(dst_smem);
    unsigned ss = ok ? 16u : 0u;
    asm volatile("cp.async.cg.shared.global [%0], [%1], 16, %2;"
                 :: "r"(saddr), "l"(src), "r"(ss));
}

__global__ __launch_bounds__(BX * BY, 4)
void conv7x7_kernel(const float* __restrict__ X,
                    const float* __restrict__ W,
                    float* __restrict__ out) {
    __shared__ __align__(16) float s_buf[2][IN_H * PITCH];
    __shared__ __align__(16) float2 s_wp[KS][2][4];   // [ky][phase][pair]

    const int tid = threadIdx.y * BX + threadIdx.x;

    // Phase-shifted weight pairs (built once per block from W):
    // phase0: {w0,w1},{w2,w3},{w4,w5},{w6,0}
    // phase1: {0,w0},{w1,w2},{w3,w4},{w5,w6}
    if (tid < KS * 8) {
        int ky = tid >> 3;
        int r  = tid & 7;
        int ph = r >> 2;
        int j  = r & 3;
        float lo, hi;
        if (ph == 0) {
            lo = W[ky * KS + 2 * j];
            hi = (2 * j + 1 < KS) ? W[ky * KS + 2 * j + 1] : 0.0f;
        } else {
            lo = (2 * j - 1 >= 0) ? W[ky * KS + 2 * j - 1] : 0.0f;
            hi = W[ky * KS + 2 * j];
        }
        s_wp[ky][ph][j] = make_float2(lo, hi);
    }

    const int tileX0 = blockIdx.x * TILE_W;
    const int yBase  = blockIdx.y * YSPAN;
    const int b      = blockIdx.z;
    const float* Xb  = X + (size_t)b * IMG * IMG;
    float* outb      = out + (size_t)b * IMG * IMG;

    const int gx0 = tileX0 - 4;           // 16B-aligned halo start

    // Per-thread cp.async addressing (hoisted; no division)
    const int c4m  = tid & 31;            // main col4 0..31
    const int r0m  = tid >> 5;            // row 0..7 (+8k)
    const int gxm  = gx0 + c4m * 4;
    const bool okxm = (gxm >= 0) && (gxm < IMG);
    const int rt_  = tid >> 1;            // tail row (tid < 76)
    const int c4t  = 32 + (tid & 1);
    const int gxt  = gx0 + c4t * 4;
    const bool okxt = (gxt < IMG);
    const bool tailact = (tid < 2 * IN_H);

    const int lx  = threadIdx.x * TX;     // local output col (multiple of 4)
    const int ly  = threadIdx.y * TY;     // local output row

#define ISSUE_CHUNK(SBUF, GY0)                                                  \
    do {                                                                        \
        const int gy0_ = (GY0);                                                 \
        _Pragma("unroll")                                                       \
        for (int k = 0; k < 5; ++k) {                                           \
            int r_ = r0m + k * 8;                                               \
            if (k < 4 || r_ < IN_H) {                                           \
                int gy_ = gy0_ + r_;                                            \
                bool ok_ = okxm && (gy_ >= 0) && (gy_ < IMG);                   \
                const float* src_ = ok_ ? (Xb + (size_t)gy_ * IMG + gxm) : Xb;  \
                cp16(&(SBUF)[r_ * PITCH + c4m * 4], src_, ok_);                 \
            }                                                                   \
        }                                                                       \
        if (tailact) {                                                          \
            int gy_ = gy0_ + rt_;                                               \
            bool ok_ = okxt && (gy_ >= 0) && (gy_ < IMG);                       \
            const float* src_ = ok_ ? (Xb + (size_t)gy_ * IMG + gxt) : Xb;      \
            cp16(&(SBUF)[rt_ * PITCH + c4t * 4], src_, ok_);                    \
        }                                                                       \
        asm volatile("cp.async.commit_group;");                                 \
    } while (0)

    // Prologue: load chunk 0
    ISSUE_CHUNK(s_buf[0], yBase - PAD);

    for (int c = 0; c < NCHUNK; ++c) {
        // One barrier per chunk: makes chunk-c data (and, on c==0, the s_wp
        // table) visible, and closes last iteration's reads of the buffer
        // that the cp.async issue below will overwrite.
        cp_wait_all();
        __syncthreads();

        if (c + 1 < NCHUNK)
            ISSUE_CHUNK(s_buf[(c + 1) & 1], yBase + (c + 1) * CHUNK_H - PAD);

        const float* buf = s_buf[c & 1];

        ull acc[TY][TX];

        // ir-outer: each input row loaded ONCE; feeds all valid
        // (ry, ky = ir - ry) cells. ky==0 cell is the first write to
        // acc[ry][*] -> mul instead of fma (no zero-init needed).
#pragma unroll
        for (int ir = 0; ir < TY + KS - 1; ++ir) {
            const ulonglong2* rowp = reinterpret_cast<const ulonglong2*>(
                &buf[(ly + ir) * PITCH + lx]);
            ulonglong2 q0 = rowp[0];   // p0, p1
            ulonglong2 q1 = rowp[1];   // p2, p3
            ulonglong2 q2 = rowp[2];   // p4, p5

#pragma unroll
            for (int ry = 0; ry < TY; ++ry) {
                const int ky = ir - ry;
                if (ky >= 0 && ky < KS) {
                    // 8 weight pairs for this ky: 4 broadcast LDS.128
                    const ulonglong2* w0p = reinterpret_cast<const ulonglong2*>(
                        &s_wp[ky][0][0]);
                    const ulonglong2* w1p = reinterpret_cast<const ulonglong2*>(
                        &s_wp[ky][1][0]);
                    ulonglong2 wA = w0p[0];   // wa0, wa1
                    ulonglong2 wB = w0p[1];   // wb0, wb1
                    ulonglong2 wC = w1p[0];   // wc0, wc1
                    ulonglong2 wD = w1p[1];   // wd0, wd1

                    if (ky == 0) {
                        // first write to acc[ry][*]
                        fmul2(acc[ry][0], q0.x, wC.x);
                        ffma2(acc[ry][0], q0.y, wC.y);
                        ffma2(acc[ry][0], q1.x, wD.x);
                        ffma2(acc[ry][0], q1.y, wD.y);

                        fmul2(acc[ry][1], q0.y, wA.x);
                        ffma2(acc[ry][1], q1.x, wA.y);
                        ffma2(acc[ry][1], q1.y, wB.x);
                        ffma2(acc[ry][1], q2.x, wB.y);

                        fmul2(acc[ry][2], q0.y, wC.x);
                        ffma2(acc[ry][2], q1.x, wC.y);
                        ffma2(acc[ry][2], q1.y, wD.x);
                        ffma2(acc[ry][2], q2.x, wD.y);

                        fmul2(acc[ry][3], q1.x, wA.x);
                        ffma2(acc[ry][3], q1.y, wA.y);
                        ffma2(acc[ry][3], q2.x, wB.x);
                        ffma2(acc[ry][3], q2.y, wB.y);
                    } else {
                        // ox=0: phase1 over p0..p3
                        ffma2(acc[ry][0], q0.x, wC.x);
                        ffma2(acc[ry][0], q0.y, wC.y);
                        ffma2(acc[ry][0], q1.x, wD.x);
                        ffma2(acc[ry][0], q1.y, wD.y);
                        // ox=1: phase0 over p1..p4
                        ffma2(acc[ry][1], q0.y, wA.x);
                        ffma2(acc[ry][1], q1.x, wA.y);
                        ffma2(acc[ry][1], q1.y, wB.x);
                        ffma2(acc[ry][1], q2.x, wB.y);
                        // ox=2: phase1 over p1..p4
                        ffma2(acc[ry][2], q0.y, wC.x);
                        ffma2(acc[ry][2], q1.x, wC.y);
                        ffma2(acc[ry][2], q1.y, wD.x);
                        ffma2(acc[ry][2], q2.x, wD.y);
                        // ox=3: phase0 over p2..p5
                        ffma2(acc[ry][3], q1.x, wA.x);
                        ffma2(acc[ry][3], q1.y, wA.y);
                        ffma2(acc[ry][3], q2.x, wB.x);
                        ffma2(acc[ry][3], q2.y, wB.y);
                    }
                }
            }
        }

        // Store chunk results (aligned float4)
        const int ox0 = tileX0 + lx;
        const int oy0 = yBase + c * CHUNK_H + ly;
#pragma unroll
        for (int ry = 0; ry < TY; ++ry) {
            float4 v;
            float lo, hi;
            unpack2(acc[ry][0], lo, hi); v.x = lo + hi;
            unpack2(acc[ry][1], lo, hi); v.y = lo + hi;
            unpack2(acc[ry][2], lo, hi); v.z = lo + hi;
            unpack2(acc[ry][3], lo, hi); v.w = lo + hi;
            *reinterpret_cast<float4*>(&outb[(size_t)(oy0 + ry) * IMG + ox0]) = v;
        }
        // No trailing __syncthreads: WAR protection comes from the barrier at
        // the top of the next iteration (cp.async issue moved after it).
    }
#undef ISSUE_CHUNK
}

extern "C" void kernel_launch(void* const* d_in, const int* in_sizes, int n_in,
                              void* d_out, int out_size) {
    const float* X = (const float*)d_in[0];
    const float* W = (const float*)d_in[1];
    float* out = (float*)d_out;

    dim3 block(BX, BY);
    dim3 grid(IMG / TILE_W, YGROUPS, 64);
    conv7x7_kernel<<<grid, block>>>(X, W, out);
}

// round 14
// speedup vs baseline: 2.4528x; 2.4528x over previous
#include <cuda_runtime.h>

// Conv2D 7x7, stride 1, pad 3. X [64,1024,1024] fp32 -> out [64,1024,1024].
// R13: barrier-free warp-private pipeline. Each warp computes 4-row x 128-col
// groups, loads its own 10-row input window (halo duplicated across warps;
// L2 absorbs) into a warp-private cp.async double buffer. Sync is
// wait_group + __syncwarp only -- NO __syncthreads anywhere.
// Compute core: validated ir-outer single-load-per-row + FFMA2 phase trick +
// constant-bank weights (R11).

#define IMG 1024
#define KS 7
#define PAD 3

#define BX 32
#define NWARP 8
#define TX 4
#define TY 4
#define TILE_W 128                 // 32 lanes * TX
#define SWEEP (NWARP * TY)         // 32 rows per sweep
#define YGROUPS 4
#define YSPAN (IMG / YGROUPS)      // 256
#define NGRP (YSPAN / SWEEP)       // 8 groups per warp

#define ROWS_IN (TY + KS - 1)      // 10 input rows per group
#define PITCH 136                  // floats per smem row (544B, 16B-aligned)
#define WBUF (ROWS_IN * PITCH)     // 1360 floats per stage
#define SMEM_BYTES (NWARP * 2 * WBUF * 4)   // 87040 B

typedef unsigned long long ull;

// Phase-pair weight tables (constant bank: validated in R7/R11).
// phase0: {w0,w1},{w2,w3},{w4,w5},{w6,0}
// phase1: {0,w0},{w1,w2},{w3,w4},{w5,w6}
__constant__ float2 cWp[KS][2][4];
__device__ float2 g_wp[KS][2][4];

__global__ void prep_weights(const float* __restrict__ W) {
    int t = threadIdx.x;
    if (t < KS * 8) {
        int ky = t >> 3;
        int r  = t & 7;
        int ph = r >> 2;
        int j  = r & 3;
        float lo, hi;
        if (ph == 0) {
            lo = W[ky * KS + 2 * j];
            hi = (2 * j + 1 < KS) ? W[ky * KS + 2 * j + 1] : 0.0f;
        } else {
            lo = (2 * j - 1 >= 0) ? W[ky * KS + 2 * j - 1] : 0.0f;
            hi = W[ky * KS + 2 * j];
        }
        g_wp[ky][ph][j] = make_float2(lo, hi);
    }
}

__device__ __forceinline__ void ffma2(ull& d, ull a, ull b) {
    asm("fma.rn.f32x2 %0, %1, %2, %0;" : "+l"(d) : "l"(a), "l"(b));
}
__device__ __forceinline__ ull pack2c(float2 v) {
    ull r;
    asm("mov.b64 %0, {%1, %2};" : "=l"(r) : "f"(v.x), "f"(v.y));
    return r;
}
__device__ __forceinline__ void unpack2(ull v, float& lo, float& hi) {
    asm("mov.b64 {%0, %1}, %2;" : "=f"(lo), "=f"(hi) : "l"(v));
}
template <int N>
__device__ __forceinline__ void cp_wait_group() {
    asm volatile("cp.async.wait_group %0;" :: "n"(N));
}
__device__ __forceinline__ void cp16(float* dst_smem, const float* src, bool ok) {
    unsigned saddr = (unsigned)__cvta_generic_to_shared(dst_smem);
    unsigned ss = ok ? 16u : 0u;
    asm volatile("cp.async.cg.shared.global [%0], [%1], 16, %2;"
                 :: "r"(saddr), "l"(src), "r"(ss));
}

__global__ __launch_bounds__(BX * NWARP, 2)
void conv7x7_kernel(const float* __restrict__ X,
                    float* __restrict__ out) {
    extern __shared__ __align__(16) float s_dyn[];

    const int lane = threadIdx.x;          // 0..31
    const int w    = threadIdx.y;          // warp id 0..7

    float* buf0 = s_dyn + (w * 2 + 0) * WBUF;   // warp-private stage 0
    float* buf1 = s_dyn + (w * 2 + 1) * WBUF;   // warp-private stage 1

    const int tileX0 = blockIdx.x * TILE_W;
    const int yBase  = blockIdx.y * YSPAN;
    const int b      = blockIdx.z;
    const float* Xb  = X + (size_t)b * IMG * IMG;
    float* outb      = out + (size_t)b * IMG * IMG;

    const int gx0 = tileX0 - 4;            // 16B-aligned halo start

    // Per-lane load addressing (hoisted). Main: col4 = lane (floats lane*4..+3).
    const int  gxm  = gx0 + lane * 4;
    const bool okxm = (gxm >= 0) && (gxm < IMG);
    // Tail: 2 float4 per row (col4 = 32,33), lanes 0..19 cover 10 rows x 2.
    const int  rT   = lane >> 1;
    const int  c4t  = 32 + (lane & 1);
    const int  gxt  = gx0 + c4t * 4;
    const bool okxt = (gxt < IMG);          // gxt >= 124 always >= 0
    const bool tailact = (lane < 2 * ROWS_IN);

    // First input row of warp's group g is gy0base + g*SWEEP.
    const int gy0base = yBase + w * TY - PAD;

#define ISSUE_GRP(BUF, GY0)                                                     \
    do {                                                                        \
        const int gy0_ = (GY0);                                                 \
        _Pragma("unroll")                                                       \
        for (int r_ = 0; r_ < ROWS_IN; ++r_) {                                  \
            int gy_ = gy0_ + r_;                                                \
            bool ok_ = okxm && ((unsigned)gy_ < IMG);                           \
            const float* src_ = ok_ ? (Xb + (size_t)gy_ * IMG + gxm) : Xb;      \
            cp16(&(BUF)[r_ * PITCH + lane * 4], src_, ok_);                     \
        }                                                                       \
        if (tailact) {                                                          \
            int gy_ = gy0_ + rT;                                                \
            bool ok_ = okxt && ((unsigned)gy_ < IMG);                           \
            const float* src_ = ok_ ? (Xb + (size_t)gy_ * IMG + gxt) : Xb;      \
            cp16(&(BUF)[rT * PITCH + c4t * 4], src_, ok_);                      \
        }                                                                       \
        asm volatile("cp.async.commit_group;");                                 \
    } while (0)

    // Prologue: load group 0 into stage 0
    ISSUE_GRP(buf0, gy0base);

    for (int g = 0; g < NGRP; ++g) {
        // Prefetch next group into the other stage, then wait for group g.
        // After the issue there are <=2 outstanding groups; wait_group<1>
        // drains group g. Cross-lane visibility via __syncwarp (each lane
        // has drained its own copies; syncwarp fences + converges the warp).
        if (g + 1 < NGRP) {
            ISSUE_GRP((((g + 1) & 1) ? buf1 : buf0),
                      gy0base + (g + 1) * SWEEP);
            cp_wait_group<1>();
        } else {
            cp_wait_group<0>();
        }
        __syncwarp();

        const float* buf = (g & 1) ? buf1 : buf0;

        ull acc[TY][TX];
#pragma unroll
        for (int ry = 0; ry < TY; ++ry)
#pragma unroll
            for (int ox = 0; ox < TX; ++ox) acc[ry][ox] = 0ull;

        // ir-outer over the 10 buffered rows; each row loaded ONCE
        // (3 aligned LDS.128 -> 6 pairs), feeding all valid (ry, ky=ir-ry).
#pragma unroll
        for (int ir = 0; ir < ROWS_IN; ++ir) {
            const ulonglong2* rowp = reinterpret_cast<const ulonglong2*>(
                &buf[ir * PITCH + lane * TX]);
            ulonglong2 q0 = rowp[0];   // p0, p1
            ulonglong2 q1 = rowp[1];   // p2, p3
            ulonglong2 q2 = rowp[2];   // p4, p5

#pragma unroll
            for (int ry = 0; ry < TY; ++ry) {
                const int ky = ir - ry;
                if (ky >= 0 && ky < KS) {
                    // 8 weight pairs for this ky from the constant bank
                    ull wa0 = pack2c(cWp[ky][0][0]);
                    ull wa1 = pack2c(cWp[ky][0][1]);
                    ull wb0 = pack2c(cWp[ky][0][2]);
                    ull wb1 = pack2c(cWp[ky][0][3]);
                    ull wc0 = pack2c(cWp[ky][1][0]);
                    ull wc1 = pack2c(cWp[ky][1][1]);
                    ull wd0 = pack2c(cWp[ky][1][2]);
                    ull wd1 = pack2c(cWp[ky][1][3]);

                    // ox=0: phase1 over p0..p3
                    ffma2(acc[ry][0], q0.x, wc0); ffma2(acc[ry][0], q0.y, wc1);
                    ffma2(acc[ry][0], q1.x, wd0); ffma2(acc[ry][0], q1.y, wd1);
                    // ox=1: phase0 over p1..p4
                    ffma2(acc[ry][1], q0.y, wa0); ffma2(acc[ry][1], q1.x, wa1);
                    ffma2(acc[ry][1], q1.y, wb0); ffma2(acc[ry][1], q2.x, wb1);
                    // ox=2: phase1 over p1..p4
                    ffma2(acc[ry][2], q0.y, wc0); ffma2(acc[ry][2], q1.x, wc1);
                    ffma2(acc[ry][2], q1.y, wd0); ffma2(acc[ry][2], q2.x, wd1);
                    // ox=3: phase0 over p2..p5
                    ffma2(acc[ry][3], q1.x, wa0); ffma2(acc[ry][3], q1.y, wa1);
                    ffma2(acc[ry][3], q2.x, wb0); ffma2(acc[ry][3], q2.y, wb1);
                }
            }
        }

        // Store group results (aligned float4); output rows gy0base+g*SWEEP+PAD+ry
        const int oy0 = gy0base + g * SWEEP + PAD;
        const int ox0 = tileX0 + lane * TX;
#pragma unroll
        for (int ry = 0; ry < TY; ++ry) {
            float4 v;
            float lo, hi;
            unpack2(acc[ry][0], lo, hi); v.x = lo + hi;
            unpack2(acc[ry][1], lo, hi); v.y = lo + hi;
            unpack2(acc[ry][2], lo, hi); v.z = lo + hi;
            unpack2(acc[ry][3], lo, hi); v.w = lo + hi;
            *reinterpret_cast<float4*>(&outb[(size_t)(oy0 + ry) * IMG + ox0]) = v;
        }
        // No barrier: next iteration's cp.async targets the stage whose last
        // readers (compute g-1, this warp, lockstep) have already consumed
        // their LDS results; warp-private buffers => no cross-warp hazard.
    }
#undef ISSUE_GRP
}

extern "C" void kernel_launch(void* const* d_in, const int* in_sizes, int n_in,
                              void* d_out, int out_size) {
    const float* X = (const float*)d_in[0];
    const float* W = (const float*)d_in[1];
    float* out = (float*)d_out;

    cudaFuncSetAttribute(conv7x7_kernel,
                         cudaFuncAttributeMaxDynamicSharedMemorySize,
                         SMEM_BYTES);

    // Build phase-pair table, stage into constant bank (D2D, graph-legal).
    prep_weights<<<1, 64>>>(W);
    void* dst = nullptr;
    void* src = nullptr;
    cudaGetSymbolAddress(&dst, cWp);
    cudaGetSymbolAddress(&src, g_wp);
    cudaMemcpyAsync(dst, src, sizeof(g_wp), cudaMemcpyDeviceToDevice);

    dim3 block(BX, NWARP);
    dim3 grid(IMG / TILE_W, YGROUPS, 64);
    conv7x7_kernel<<<grid, block, SMEM_BYTES>>>(X, out);
}

// round 15
// speedup vs baseline: 2.8592x; 1.1657x over previous
#include <cuda_runtime.h>

// Conv2D 7x7, stride 1, pad 3. X [64,1024,1024] fp32 -> out [64,1024,1024].
// R15: R11 per-warp economics (ir-outer single-load-per-row + FFMA2 phase
// trick + constant-bank weights + cp.async double-buffer, one barrier/chunk)
// rescheduled as SMALL blocks: 128 threads, CHUNK_H=16, 8-9 blocks/SM.
// Same resident warps as R11 but 2x more independent blocks per SM ->
// bulk-synchronous phases decorrelate and the fma pipe stays fed.

#define IMG 1024
#define KS 7
#define PAD 3

#define BX 32
#define BY 4
#define TX 4
#define TY 4
#define NTHREADS (BX * BY)         // 128
#define TILE_W (BX * TX)           // 128
#define CHUNK_H (BY * TY)          // 16 output rows per chunk
#define YGROUPS 8
#define YSPAN (IMG / YGROUPS)      // 128
#define NCHUNK (YSPAN / CHUNK_H)   // 8

#define IN_H (CHUNK_H + KS - 1)    // 22 input rows per chunk
#define PITCH 136                  // floats per smem row (544B, 16B-aligned)

typedef unsigned long long ull;

// Phase-pair weight tables (constant bank; validated R7/R11).
// phase0: {w0,w1},{w2,w3},{w4,w5},{w6,0}
// phase1: {0,w0},{w1,w2},{w3,w4},{w5,w6}
__constant__ float2 cWp[KS][2][4];
__device__ float2 g_wp[KS][2][4];

__global__ void prep_weights(const float* __restrict__ W) {
    int t = threadIdx.x;
    if (t < KS * 8) {
        int ky = t >> 3;
        int r  = t & 7;
        int ph = r >> 2;
        int j  = r & 3;
        float lo, hi;
        if (ph == 0) {
            lo = W[ky * KS + 2 * j];
            hi = (2 * j + 1 < KS) ? W[ky * KS + 2 * j + 1] : 0.0f;
        } else {
            lo = (2 * j - 1 >= 0) ? W[ky * KS + 2 * j - 1] : 0.0f;
            hi = W[ky * KS + 2 * j];
        }
        g_wp[ky][ph][j] = make_float2(lo, hi);
    }
}

__device__ __forceinline__ void ffma2(ull& d, ull a, ull b) {
    asm("fma.rn.f32x2 %0, %1, %2, %0;" : "+l"(d) : "l"(a), "l"(b));
}
__device__ __forceinline__ ull pack2c(float2 v) {
    ull r;
    asm("mov.b64 %0, {%1, %2};" : "=l"(r) : "f"(v.x), "f"(v.y));
    return r;
}
__device__ __forceinline__ void unpack2(ull v, float& lo, float& hi) {
    asm("mov.b64 {%0, %1}, %2;" : "=f"(lo), "=f"(hi) : "l"(v));
}
__device__ __forceinline__ void cp_wait_all() {
    asm volatile("cp.async.wait_group 0;");
}
__device__ __forceinline__ void cp16(float* dst_smem, const float* src, bool ok) {
    unsigned saddr = (unsigned)__cvta_generic_to_shared(dst_smem);
    unsigned ss = ok ? 16u : 0u;
    asm volatile("cp.async.cg.shared.global [%0], [%1], 16, %2;"
                 :: "r"(saddr), "l"(src), "r"(ss));
}

__global__ __launch_bounds__(NTHREADS, 9)
void conv7x7_kernel(const float* __restrict__ X,
                    float* __restrict__ out) {
    __shared__ __align__(16) float s_buf[2][IN_H * PITCH];

    const int tid = threadIdx.y * BX + threadIdx.x;

    const int tileX0 = blockIdx.x * TILE_W;
    const int yBase  = blockIdx.y * YSPAN;
    const int b      = blockIdx.z;
    const float* Xb  = X + (size_t)b * IMG * IMG;
    float* outb      = out + (size_t)b * IMG * IMG;

    const int gx0 = tileX0 - 4;           // 16B-aligned halo start

    // Per-thread cp.async addressing (hoisted; no division).
    // Main: 32 col4 x 22 rows; c4 = tid&31, row r0m + 4k (k<6, r<22).
    const int c4m  = tid & 31;
    const int r0m  = tid >> 5;            // 0..3
    const int gxm  = gx0 + c4m * 4;
    const bool okxm = (gxm >= 0) && (gxm < IMG);
    // Tail: col4 32,33 for 22 rows; lanes tid<44.
    const int rt_  = tid >> 1;
    const int c4t  = 32 + (tid & 1);
    const int gxt  = gx0 + c4t * 4;
    const bool okxt = (gxt < IMG);
    const bool tailact = (tid < 2 * IN_H);

    const int lx  = threadIdx.x * TX;     // local output col (multiple of 4)
    const int ly  = threadIdx.y * TY;     // local output row (0,4,8,12)

#define ISSUE_CHUNK(SBUF, GY0)                                                  \
    do {                                                                        \
        const int gy0_ = (GY0);                                                 \
        _Pragma("unroll")                                                       \
        for (int k = 0; k < 6; ++k) {                                           \
            int r_ = r0m + k * 4;                                               \
            if (k < 5 || r_ < IN_H) {                                           \
                int gy_ = gy0_ + r_;                                            \
                bool ok_ = okxm && ((unsigned)gy_ < IMG);                       \
                const float* src_ = ok_ ? (Xb + (size_t)gy_ * IMG + gxm) : Xb;  \
                cp16(&(SBUF)[r_ * PITCH + c4m * 4], src_, ok_);                 \
            }                                                                   \
        }                                                                       \
        if (tailact) {                                                          \
            int gy_ = gy0_ + rt_;                                               \
            bool ok_ = okxt && ((unsigned)gy_ < IMG);                           \
            const float* src_ = ok_ ? (Xb + (size_t)gy_ * IMG + gxt) : Xb;      \
            cp16(&(SBUF)[rt_ * PITCH + c4t * 4], src_, ok_);                    \
        }                                                                       \
        asm volatile("cp.async.commit_group;");                                 \
    } while (0)

    // Prologue: load chunk 0
    ISSUE_CHUNK(s_buf[0], yBase - PAD);

    for (int c = 0; c < NCHUNK; ++c) {
        // One barrier per chunk: publishes chunk-c data and closes last
        // iteration's reads of the buffer the next cp.async will overwrite.
        cp_wait_all();
        __syncthreads();

        if (c + 1 < NCHUNK)
            ISSUE_CHUNK(s_buf[(c + 1) & 1], yBase + (c + 1) * CHUNK_H - PAD);

        const float* buf = s_buf[c & 1];

        ull acc[TY][TX];
#pragma unroll
        for (int ry = 0; ry < TY; ++ry)
#pragma unroll
            for (int ox = 0; ox < TX; ++ox) acc[ry][ox] = 0ull;

        // ir-outer: each input row loaded ONCE (3 aligned LDS.128 -> 6 pairs);
        // feeds all valid (ry, ky = ir - ry). Guards are compile-time.
#pragma unroll
        for (int ir = 0; ir < TY + KS - 1; ++ir) {
            const ulonglong2* rowp = reinterpret_cast<const ulonglong2*>(
                &buf[(ly + ir) * PITCH + lx]);
            ulonglong2 q0 = rowp[0];   // p0, p1
            ulonglong2 q1 = rowp[1];   // p2, p3
            ulonglong2 q2 = rowp[2];   // p4, p5

#pragma unroll
            for (int ry = 0; ry < TY; ++ry) {
                const int ky = ir - ry;
                if (ky >= 0 && ky < KS) {
                    // 8 weight pairs for this ky from the constant bank
                    ull wa0 = pack2c(cWp[ky][0][0]);
                    ull wa1 = pack2c(cWp[ky][0][1]);
                    ull wb0 = pack2c(cWp[ky][0][2]);
                    ull wb1 = pack2c(cWp[ky][0][3]);
                    ull wc0 = pack2c(cWp[ky][1][0]);
                    ull wc1 = pack2c(cWp[ky][1][1]);
                    ull wd0 = pack2c(cWp[ky][1][2]);
                    ull wd1 = pack2c(cWp[ky][1][3]);

                    // ox=0: phase1 over p0..p3
                    ffma2(acc[ry][0], q0.x, wc0); ffma2(acc[ry][0], q0.y, wc1);
                    ffma2(acc[ry][0], q1.x, wd0); ffma2(acc[ry][0], q1.y, wd1);
                    // ox=1: phase0 over p1..p4
                    ffma2(acc[ry][1], q0.y, wa0); ffma2(acc[ry][1], q1.x, wa1);
                    ffma2(acc[ry][1], q1.y, wb0); ffma2(acc[ry][1], q2.x, wb1);
                    // ox=2: phase1 over p1..p4
                    ffma2(acc[ry][2], q0.y, wc0); ffma2(acc[ry][2], q1.x, wc1);
                    ffma2(acc[ry][2], q1.y, wd0); ffma2(acc[ry][2], q2.x, wd1);
                    // ox=3: phase0 over p2..p5
                    ffma2(acc[ry][3], q1.x, wa0); ffma2(acc[ry][3], q1.y, wa1);
                    ffma2(acc[ry][3], q2.x, wb0); ffma2(acc[ry][3], q2.y, wb1);
                }
            }
        }

        // Store chunk results (aligned float4)
        const int ox0 = tileX0 + lx;
        const int oy0 = yBase + c * CHUNK_H + ly;
#pragma unroll
        for (int ry = 0; ry < TY; ++ry) {
            float4 v;
            float lo, hi;
            unpack2(acc[ry][0], lo, hi); v.x = lo + hi;
            unpack2(acc[ry][1], lo, hi); v.y = lo + hi;
            unpack2(acc[ry][2], lo, hi); v.z = lo + hi;
            unpack2(acc[ry][3], lo, hi); v.w = lo + hi;
            *reinterpret_cast<float4*>(&outb[(size_t)(oy0 + ry) * IMG + ox0]) = v;
        }
        // No trailing __syncthreads: WAR protection comes from the barrier at
        // the top of the next iteration (cp.async issue moved after it).
    }
#undef ISSUE_CHUNK
}

extern "C" void kernel_launch(void* const* d_in, const int* in_sizes, int n_in,
                              void* d_out, int out_size) {
    const float* X = (const float*)d_in[0];
    const float* W = (const float*)d_in[1];
    float* out = (float*)d_out;

    // Build phase-pair table, stage into constant bank (D2D, graph-legal).
    prep_weights<<<1, 64>>>(W);
    void* dst = nullptr;
    void* src = nullptr;
    cudaGetSymbolAddress(&dst, cWp);
    cudaGetSymbolAddress(&src, g_wp);
    cudaMemcpyAsync(dst, src, sizeof(g_wp), cudaMemcpyDeviceToDevice);

    dim3 block(BX, BY);
    dim3 grid(IMG / TILE_W, YGROUPS, 64);
    conv7x7_kernel<<<grid, block>>>(X, out);
}